// round 2
// baseline (speedup 1.0000x reference)
#include <cuda_runtime.h>
#include <cstddef>

// Problem constants (fixed by the dataset)
#define Fk   51
#define HOo  512
#define WOo  512
#define CC   3
#define HIN  562   // HO + F - 1
#define WIN  562
#define BB   2

// Tiling
#define TXX  32          // output x per block (== warp width)
#define WYY  4           // y-groups (threadIdx.y)
#define RYY  2           // outputs per thread in y
#define TYY  (WYY * RYY) // 8 output rows per block
#define TILE_ROWS (TYY + Fk - 1)   // 58
#define TILE_COLS (TXX + Fk - 1)   // 82

__global__ __launch_bounds__(TXX * WYY, 2)
void sepconv_kernel(const float* __restrict__ inp,
                    const float* __restrict__ vert,
                    const float* __restrict__ horz,
                    float* __restrict__ out)
{
    __shared__ float tile[TILE_ROWS * TILE_COLS];

    const int b   = blockIdx.z;
    const int x0  = blockIdx.x * TXX;
    const int y0  = blockIdx.y * TYY;
    const int tx  = threadIdx.x;
    const int ty  = threadIdx.y;
    const int tid = ty * TXX + tx;

    const int x  = x0 + tx;
    const int yA = y0 + ty * RYY;
    const int yB = yA + 1;

    // ---- Preload both horizontal filter vectors into registers (102 regs) ----
    float hA[Fk], hB[Fk];
    {
        const float* hp = horz + (size_t)b * Fk * HOo * WOo;
        #pragma unroll
        for (int j = 0; j < Fk; ++j) {
            hA[j] = __ldg(hp + ((size_t)j * HOo + yA) * WOo + x);
            hB[j] = __ldg(hp + ((size_t)j * HOo + yB) * WOo + x);
        }
    }

    // vertical[b, i, y, x] base pointers; i-stride = HOo*WOo
    const float* vA_ptr = vert + (size_t)b * Fk * HOo * WOo + (size_t)yA * WOo + x;
    const float* vB_ptr = vert + (size_t)b * Fk * HOo * WOo + (size_t)yB * WOo + x;

    #pragma unroll 1
    for (int c = 0; c < CC; ++c) {
        // ---- Cooperative input tile load for this channel ----
        const float* gsrc = inp + (((size_t)b * CC + c) * HIN + y0) * WIN + x0;
        __syncthreads();   // protect prior iteration's tile reads
        #pragma unroll 1
        for (int idx = tid; idx < TILE_ROWS * TILE_COLS; idx += TXX * WYY) {
            int r   = idx / TILE_COLS;
            int col = idx - r * TILE_COLS;
            tile[idx] = gsrc[(size_t)r * WIN + col];
        }
        __syncthreads();

        float accA = 0.f, accB = 0.f;

        // Input rows rr = 0 .. F+RY-2 relative to yA.
        // Row rr contributes to output A with i=rr (rr<F) and to B with i=rr-1 (rr>=1).
        #pragma unroll 1
        for (int rr = 0; rr < Fk + RYY - 1; ++rr) {
            const float* row = tile + (ty * RYY + rr) * TILE_COLS + tx;

            // Two dot products of the same smem row against hA and hB:
            // each smem float feeds 2 FMAs (the RY=2 reuse that balances LDS vs FMA).
            float tA0 = 0.f, tA1 = 0.f, tA2 = 0.f, tA3 = 0.f;
            float tB0 = 0.f, tB1 = 0.f, tB2 = 0.f, tB3 = 0.f;
            #pragma unroll
            for (int j = 0; j < Fk; ++j) {
                float in = row[j];
                if ((j & 3) == 0) { tA0 = fmaf(in, hA[j], tA0); tB0 = fmaf(in, hB[j], tB0); }
                if ((j & 3) == 1) { tA1 = fmaf(in, hA[j], tA1); tB1 = fmaf(in, hB[j], tB1); }
                if ((j & 3) == 2) { tA2 = fmaf(in, hA[j], tA2); tB2 = fmaf(in, hB[j], tB2); }
                if ((j & 3) == 3) { tA3 = fmaf(in, hA[j], tA3); tB3 = fmaf(in, hB[j], tB3); }
            }
            float tmpA = (tA0 + tA1) + (tA2 + tA3);
            float tmpB = (tB0 + tB1) + (tB2 + tB3);

            if (rr < Fk)
                accA = fmaf(__ldg(vA_ptr + (size_t)rr * (HOo * WOo)), tmpA, accA);
            if (rr >= 1)
                accB = fmaf(__ldg(vB_ptr + (size_t)(rr - 1) * (HOo * WOo)), tmpB, accB);
        }

        out[(((size_t)b * CC + c) * HOo + yA) * WOo + x] = accA;
        out[(((size_t)b * CC + c) * HOo + yB) * WOo + x] = accB;
    }
}

extern "C" void kernel_launch(void* const* d_in, const int* in_sizes, int n_in,
                              void* d_out, int out_size)
{
    // Expected order: input (B*C*HIN*WIN), vertical, horizontal.
    // Defensive: identify 'input' by its distinctive element count; keep the
    // relative order of the two filter tensors (vertical before horizontal).
    const int input_elems = BB * CC * HIN * WIN;   // 1,895,064
    int idx_in = 0;
    for (int i = 0; i < n_in; ++i)
        if (in_sizes[i] == input_elems) { idx_in = i; break; }
    int idx_v = -1, idx_h = -1;
    for (int i = 0; i < n_in; ++i) {
        if (i == idx_in) continue;
        if (idx_v < 0) idx_v = i; else if (idx_h < 0) idx_h = i;
    }

    const float* inp  = (const float*)d_in[idx_in];
    const float* vert = (const float*)d_in[idx_v];
    const float* horz = (const float*)d_in[idx_h];
    float* o = (float*)d_out;

    dim3 block(TXX, WYY, 1);
    dim3 grid(WOo / TXX, HOo / TYY, BB);   // (16, 64, 2)
    sepconv_kernel<<<grid, block>>>(inp, vert, horz, o);
}

// round 4
// speedup vs baseline: 1.2710x; 1.2710x over previous
#include <cuda_runtime.h>
#include <cstddef>

// Problem constants (fixed by the dataset)
#define Fk   51
#define HOo  512
#define WOo  512
#define CC   3
#define HIN  562   // HO + F - 1
#define WIN  562
#define BB   2
#define HW   (HOo * WOo)

// Tiling
#define TXX  32          // output x per block (== warp width)
#define WYY  4           // y-groups (threadIdx.y)
#define RYY  4           // outputs per thread in y
#define TYY  (WYY * RYY) // 16 output rows per block
#define TILE_ROWS (TYY + Fk - 1)   // 66
#define TILE_COLS (TXX + Fk - 1)   // 82

typedef unsigned long long u64;

// ---- packed f32x2 helpers (Blackwell FFMA2 path) ----
__device__ __forceinline__ u64 pack2(float lo, float hi) {
    u64 r;
    asm("mov.b64 %0, {%1, %2};" : "=l"(r) : "f"(lo), "f"(hi));
    return r;
}
__device__ __forceinline__ void unpack2(u64 v, float& lo, float& hi) {
    asm("mov.b64 {%0, %1}, %2;" : "=f"(lo), "=f"(hi) : "l"(v));
}
__device__ __forceinline__ void ffma2(u64& d, u64 a, u64 b) {
    // d = a * b + d  (elementwise on packed f32x2)
    asm("fma.rn.f32x2 %0, %1, %2, %0;" : "+l"(d) : "l"(a), "l"(b));
}
__device__ __forceinline__ u64 fadd2(u64 a, u64 b) {
    u64 r;
    asm("add.rn.f32x2 %0, %1, %2;" : "=l"(r) : "l"(a), "l"(b));
    return r;
}

__global__ __launch_bounds__(TXX * WYY, 2)
void sepconv_kernel(const float* __restrict__ inp,
                    const float* __restrict__ vert,
                    const float* __restrict__ horz,
                    float* __restrict__ out)
{
    __shared__ float tile[TILE_ROWS * TILE_COLS];

    const int b   = blockIdx.z;
    const int x0  = blockIdx.x * TXX;
    const int y0  = blockIdx.y * TYY;
    const int tx  = threadIdx.x;
    const int ty  = threadIdx.y;
    const int tid = ty * TXX + tx;

    const int x  = x0 + tx;
    const int yA = y0 + ty * RYY;    // thread outputs rows yA .. yA+3

    // ---- Preload 4 horizontal filter vectors, packed as f32x2 pairs ----
    // h2AB[j] = {h[j,yA], h[j,yA+1]},  h2CD[j] = {h[j,yA+2], h[j,yA+3]}
    u64 h2AB[Fk], h2CD[Fk];
    {
        const float* hp = horz + (size_t)b * Fk * HW + (size_t)yA * WOo + x;
        #pragma unroll
        for (int j = 0; j < Fk; ++j) {
            const float* p = hp + (size_t)j * HW;
            float a0 = __ldg(p);
            float a1 = __ldg(p + WOo);
            float a2 = __ldg(p + 2 * WOo);
            float a3 = __ldg(p + 3 * WOo);
            h2AB[j] = pack2(a0, a1);
            h2CD[j] = pack2(a2, a3);
        }
    }

    // vertical[b, i, y, x]; i-stride = HW, y-stride = WOo
    const float* v_base = vert + (size_t)b * Fk * HW + (size_t)yA * WOo + x;

    #pragma unroll 1
    for (int c = 0; c < CC; ++c) {
        // ---- Cooperative input tile load for this channel ----
        const float* gsrc = inp + (((size_t)b * CC + c) * HIN + y0) * WIN + x0;
        __syncthreads();   // protect prior iteration's tile reads
        #pragma unroll 1
        for (int idx = tid; idx < TILE_ROWS * TILE_COLS; idx += TXX * WYY) {
            int r   = idx / TILE_COLS;
            int col = idx - r * TILE_COLS;
            tile[idx] = gsrc[(size_t)r * WIN + col];
        }
        __syncthreads();

        u64 accAB = 0ULL;   // {accA, accB} packed f32x2 (bit pattern 0 == {0f,0f})
        u64 accCD = 0ULL;

        // Input rows rr = 0 .. F+RY-2 relative to yA.
        // Row rr contributes: A with i=rr (rr<=50), B with i=rr-1 (1<=rr<=51),
        //                     C with i=rr-2 (2<=rr<=52), D with i=rr-3 (3<=rr<=53)
        #pragma unroll 1
        for (int rr = 0; rr < Fk + RYY - 1; ++rr) {
            const float* row = tile + (ty * RYY + rr) * TILE_COLS + tx;

            // Predicated vertical-weight loads (issued early, consumed after j-loop)
            float vA = 0.f, vB = 0.f, vC = 0.f, vD = 0.f;
            if (rr < Fk)                   vA = __ldg(v_base + (size_t)rr * HW);
            if (rr >= 1 && rr <= Fk)       vB = __ldg(v_base + (size_t)(rr - 1) * HW + WOo);
            if (rr >= 2 && rr <= Fk + 1)   vC = __ldg(v_base + (size_t)(rr - 2) * HW + 2 * WOo);
            if (rr >= 3)                   vD = __ldg(v_base + (size_t)(rr - 3) * HW + 3 * WOo);

            // 4 packed dot products over 51 taps; each LDS feeds 2 FFMA2 = 16 FLOPs/lane
            u64 tAB0 = 0ULL, tAB1 = 0ULL, tCD0 = 0ULL, tCD1 = 0ULL;
            #pragma unroll
            for (int j = 0; j < Fk; ++j) {
                float in = row[j];
                u64 in2 = pack2(in, in);
                if (j & 1) { ffma2(tAB1, in2, h2AB[j]); ffma2(tCD1, in2, h2CD[j]); }
                else       { ffma2(tAB0, in2, h2AB[j]); ffma2(tCD0, in2, h2CD[j]); }
            }
            u64 tAB = fadd2(tAB0, tAB1);
            u64 tCD = fadd2(tCD0, tCD1);

            // acc += v * tmp (packed)
            ffma2(accAB, pack2(vA, vB), tAB);
            ffma2(accCD, pack2(vC, vD), tCD);
        }

        float oA, oB, oC, oD;
        unpack2(accAB, oA, oB);
        unpack2(accCD, oC, oD);
        float* op = out + (((size_t)b * CC + c) * HOo + yA) * WOo + x;
        op[0]               = oA;
        op[WOo]             = oB;
        op[2 * (size_t)WOo] = oC;
        op[3 * (size_t)WOo] = oD;
    }
}

extern "C" void kernel_launch(void* const* d_in, const int* in_sizes, int n_in,
                              void* d_out, int out_size)
{
    // Identify 'input' by element count; keep relative order of vertical/horizontal.
    const int input_elems = BB * CC * HIN * WIN;   // 1,895,064
    int idx_in = 0;
    for (int i = 0; i < n_in; ++i)
        if (in_sizes[i] == input_elems) { idx_in = i; break; }
    int idx_v = -1, idx_h = -1;
    for (int i = 0; i < n_in; ++i) {
        if (i == idx_in) continue;
        if (idx_v < 0) idx_v = i; else if (idx_h < 0) idx_h = i;
    }

    const float* inp  = (const float*)d_in[idx_in];
    const float* vert = (const float*)d_in[idx_v];
    const float* horz = (const float*)d_in[idx_h];
    float* o = (float*)d_out;

    dim3 block(TXX, WYY, 1);
    dim3 grid(WOo / TXX, HOo / TYY, BB);   // (16, 32, 2)
    sepconv_kernel<<<grid, block>>>(inp, vert, horz, o);
}